// round 7
// baseline (speedup 1.0000x reference)
#include <cuda_runtime.h>

// Persistent STPN, packed f32x2, per-GROUP pipelining with PROVEN sync
// mechanics: strong ld.acquire.gpu polling (R5/R6 hung with weak .cg polls),
// per-warp st.release flags, named barrier per 2-warp group.
// Warp = (1 h-row, 4 batches); group = 2 warps (both rows, same 4 batches).
// Groups progress independently -> barrier latency overlapped by other groups.

#define NCTA 128
#define NTHR 512

namespace {
constexpr int kB = 32;
constexpr int kS = 64;
constexpr int kI = 256;
constexpr int kH = 256;
constexpr int kO = 128;
constexpr int kF = 512;
}

typedef unsigned long long u64;

__device__ unsigned g_wflags[16 * NCTA];   // [wid][cta], monotonic
__device__ float g_hbuf[3][kB * kH];       // triple-buffered hidden state

__device__ __forceinline__ unsigned ld_acq(const unsigned* p) {
  unsigned v;
  asm volatile("ld.acquire.gpu.u32 %0, [%1];" : "=r"(v) : "l"(p) : "memory");
  return v;
}
__device__ __forceinline__ void st_rel(unsigned* p, unsigned v) {
  asm volatile("st.release.gpu.u32 [%0], %1;" :: "l"(p), "r"(v) : "memory");
}
__device__ __forceinline__ void wait_ge(const unsigned* p, unsigned tg) {
  while ((int)(ld_acq(p) - tg) < 0) { }
}
__device__ __forceinline__ void bar_sync(int id, int cnt) {
  asm volatile("bar.sync %0, %1;" :: "r"(id), "r"(cnt) : "memory");
}
__device__ __forceinline__ u64 fma2(u64 a, u64 b, u64 c) {
  u64 d; asm("fma.rn.f32x2 %0, %1, %2, %3;" : "=l"(d) : "l"(a), "l"(b), "l"(c));
  return d;
}
__device__ __forceinline__ u64 mul2(u64 a, u64 b) {
  u64 d; asm("mul.rn.f32x2 %0, %1, %2;" : "=l"(d) : "l"(a), "l"(b));
  return d;
}
__device__ __forceinline__ u64 pack2(float lo, float hi) {
  u64 d; asm("mov.b64 %0, {%1, %2};" : "=l"(d) : "f"(lo), "f"(hi));
  return d;
}
__device__ __forceinline__ float2 unpack2(u64 v) {
  float2 r; asm("mov.b64 {%0, %1}, %2;" : "=f"(r.x), "=f"(r.y) : "l"(v));
  return r;
}
__device__ __forceinline__ float tanh_fast(float z) {
  float e = __expf(2.0f * z);
  return 1.0f - __fdividef(2.0f, e + 1.0f);
}

__global__ void __launch_bounds__(NTHR, 1) stpn_kernel(
    const float* __restrict__ x,
    const float* __restrict__ W,
    const float* __restrict__ Lm,
    const float* __restrict__ Gm,
    const float* __restrict__ bias,
    const float* __restrict__ ow,
    const float* __restrict__ ob,
    float* __restrict__ out)
{
  __shared__ float sw[2][kF];
  __shared__ float sl[2][kF];
  __shared__ float sg[2][kF];
  __shared__ unsigned s_base;

  const int tid  = threadIdx.x;
  const int lane = tid & 31;
  const int wid  = tid >> 5;        // 0..15
  const int row_par = wid & 1;
  const int grp  = wid >> 1;        // 0..7: warps 2g, 2g+1 are tids [64g,64g+64)
  const int hr0  = blockIdx.x * 2;
  const int row  = hr0 + row_par;
  const int b0   = grp * 4;

  for (int i = tid; i < 2 * kF; i += NTHR) {
    const int r = i >> 9, c = i & 511;
    sw[r][c] = W[(hr0 + r) * kF + c];
    sl[r][c] = Lm[(hr0 + r) * kF + c];
    sg[r][c] = Gm[(hr0 + r) * kF + c];
  }
  if (tid == 0) s_base = __ldcg(&g_wflags[blockIdx.x]);
  const float bias_row = bias[row];
  __syncthreads();
  const unsigned base = s_base;

  const u64* swp = (const u64*)&sw[row_par][0];  // 256 u64
  const u64* slp = (const u64*)&sl[row_par][0];
  const u64* sgp = (const u64*)&sg[row_par][0];

  const unsigned* fgrp = g_wflags + (2 * grp) * NCTA;  // 2*128 flags for group
  unsigned* myflag = g_wflags + wid * NCTA + blockIdx.x;
  const int jj = tid & 63;          // thread index within the group

  // state u = w + f; uu[b][2k+j] covers cols 128k + 4*lane + 2j(+1). f=0 -> u=w
  u64 uu[4][8];
#pragma unroll
  for (int q = 0; q < 8; ++q) {
    const u64 wv = swp[64 * (q >> 1) + 2 * lane + (q & 1)];
#pragma unroll
    for (int b = 0; b < 4; ++b) uu[b][q] = wv;
  }

  float iv[4];
  {
    u64 sp = mul2(uu[0][0], uu[0][0]);
#pragma unroll
    for (int q = 1; q < 8; ++q) sp = fma2(uu[0][q], uu[0][q], sp);
    float2 a = unpack2(sp);
    float s = a.x + a.y;
#pragma unroll
    for (int off = 16; off; off >>= 1) s += __shfl_xor_sync(0xffffffffu, s, off);
    const float v = rsqrtf(s);
#pragma unroll
    for (int b = 0; b < 4; ++b) iv[b] = v;
  }

  float hn[4] = {0.f, 0.f, 0.f, 0.f};
  int wb = 0, rb = 2;
  const float* xb = x + (size_t)b0 * kS * kI;

  for (int t = 0; t < kS; ++t) {
    // ---- group-local wait: all 256 group flags >= t (strong acquire polls) ----
    if (t > 0) {
      const unsigned tg = base + (unsigned)t;
      wait_ge(fgrp + 2 * jj, tg);
      wait_ge(fgrp + 2 * jj + 1, tg);
      wait_ge(fgrp + NCTA + 2 * jj, tg);
      wait_ge(fgrp + NCTA + 2 * jj + 1, tg);
      bar_sync(1 + grp, 64);   // broadcast acquires within the group
    }

    // ---- pre = ti . u ----
    float pre[4];
#pragma unroll
    for (int b = 0; b < 4; ++b) {
      const u64* xp = (const u64*)(xb + ((size_t)b * kS + t) * kI);
      const u64* hp = (const u64*)(&g_hbuf[rb][(b0 + b) * kH]);
      const u64 t0 = xp[2 * lane],      t1 = xp[2 * lane + 1];
      const u64 t2 = xp[64 + 2 * lane], t3 = xp[64 + 2 * lane + 1];
      u64 h0 = 0, h1 = 0, h2 = 0, h3 = 0;
      if (t > 0) {
        h0 = __ldcg(hp + 2 * lane);      h1 = __ldcg(hp + 2 * lane + 1);
        h2 = __ldcg(hp + 64 + 2 * lane); h3 = __ldcg(hp + 64 + 2 * lane + 1);
      }
      u64 acc = mul2(t0, uu[b][0]);
      acc = fma2(t1, uu[b][1], acc);
      acc = fma2(t2, uu[b][2], acc);
      acc = fma2(t3, uu[b][3], acc);
      acc = fma2(h0, uu[b][4], acc);
      acc = fma2(h1, uu[b][5], acc);
      acc = fma2(h2, uu[b][6], acc);
      acc = fma2(h3, uu[b][7], acc);
      float2 a = unpack2(acc);
      pre[b] = a.x + a.y;
    }
#pragma unroll
    for (int off = 16; off; off >>= 1) {
      pre[0] += __shfl_xor_sync(0xffffffffu, pre[0], off);
      pre[1] += __shfl_xor_sync(0xffffffffu, pre[1], off);
      pre[2] += __shfl_xor_sync(0xffffffffu, pre[2], off);
      pre[3] += __shfl_xor_sync(0xffffffffu, pre[3], off);
    }
#pragma unroll
    for (int b = 0; b < 4; ++b)
      hn[b] = tanh_fast(fmaf(pre[b], iv[b], bias_row));

    // ---- publish: same-thread stores + release of own flag ----
    if (lane == 0) {
      __stcg(&g_hbuf[wb][(b0 + 0) * kH + row], hn[0]);
      __stcg(&g_hbuf[wb][(b0 + 1) * kH + row], hn[1]);
      __stcg(&g_hbuf[wb][(b0 + 2) * kH + row], hn[2]);
      __stcg(&g_hbuf[wb][(b0 + 3) * kH + row], hn[3]);
      st_rel(myflag, base + (unsigned)(t + 1));
    }

    // ---- shadow: u' = w + (lam*iv)*(u-w) + (gam*hn)*ti ; sq ----
    {
      const u64 n1 = pack2(-1.0f, -1.0f);
      u64 ivp[4], ghp[4], sq[4];
#pragma unroll
      for (int b = 0; b < 4; ++b) {
        ivp[b] = pack2(iv[b], iv[b]);
        ghp[b] = pack2(hn[b], hn[b]);
        sq[b]  = 0;
      }
#pragma unroll
      for (int k = 0; k < 4; ++k) {
        const int p = 64 * k + 2 * lane;
        const u64 w0 = swp[p], w1 = swp[p + 1];
        const u64 l0 = slp[p], l1 = slp[p + 1];
        const u64 g0 = sgp[p], g1 = sgp[p + 1];
#pragma unroll
        for (int b = 0; b < 4; ++b) {
          u64 ti0, ti1;
          if (k < 2) {
            const u64* xp = (const u64*)(xb + ((size_t)b * kS + t) * kI);
            ti0 = xp[64 * k + 2 * lane];
            ti1 = xp[64 * k + 2 * lane + 1];
          } else if (t > 0) {
            const u64* hp = (const u64*)(&g_hbuf[rb][(b0 + b) * kH]);
            ti0 = __ldcg(hp + 64 * (k - 2) + 2 * lane);
            ti1 = __ldcg(hp + 64 * (k - 2) + 2 * lane + 1);
          } else {
            ti0 = 0; ti1 = 0;
          }
          u64& Ua = uu[b][2 * k];
          u64& Ub = uu[b][2 * k + 1];
          {
            const u64 a = mul2(l0, ivp[b]);
            const u64 d = fma2(n1, w0, Ua);
            const u64 e = fma2(mul2(g0, ghp[b]), ti0, w0);
            Ua = fma2(a, d, e);
            sq[b] = fma2(Ua, Ua, sq[b]);
          }
          {
            const u64 a = mul2(l1, ivp[b]);
            const u64 d = fma2(n1, w1, Ub);
            const u64 e = fma2(mul2(g1, ghp[b]), ti1, w1);
            Ub = fma2(a, d, e);
            sq[b] = fma2(Ub, Ub, sq[b]);
          }
        }
      }
      float s[4];
#pragma unroll
      for (int b = 0; b < 4; ++b) {
        float2 a = unpack2(sq[b]);
        s[b] = a.x + a.y;
      }
#pragma unroll
      for (int off = 16; off; off >>= 1) {
        s[0] += __shfl_xor_sync(0xffffffffu, s[0], off);
        s[1] += __shfl_xor_sync(0xffffffffu, s[1], off);
        s[2] += __shfl_xor_sync(0xffffffffu, s[2], off);
        s[3] += __shfl_xor_sync(0xffffffffu, s[3], off);
      }
#pragma unroll
      for (int b = 0; b < 4; ++b) iv[b] = rsqrtf(s[b]);
    }

    rb = wb;
    wb = (wb == 2) ? 0 : wb + 1;
  }

  // ---------------- epilogue (per-warp independent) ----------------
  {
    const u64 n1 = pack2(-1.0f, -1.0f);
    u64* fout = (u64*)(out + kB * kO + kB * kH);
#pragma unroll
    for (int b = 0; b < 4; ++b) {
      u64* rowp = fout + (size_t)((b0 + b) * kH + row) * (kF / 2);
#pragma unroll
      for (int q = 0; q < 8; ++q) {
        const int p = 64 * (q >> 1) + 2 * lane + (q & 1);
        rowp[p] = fma2(n1, swp[p], uu[b][q]);
      }
    }
  }
  if (lane == 0) {
#pragma unroll
    for (int b = 0; b < 4; ++b)
      out[kB * kO + (b0 + b) * kH + row] = hn[b];
  }

  // tag_space on CTAs 0..31: wait for ALL 2048 warp-flags to reach base+64
  if (blockIdx.x < kB) {
    {
      const unsigned target = base + (unsigned)kS;
      const unsigned* fp = g_wflags + 4 * tid;   // 512 threads x 4 = 2048
      wait_ge(fp + 0, target);
      wait_ge(fp + 1, target);
      wait_ge(fp + 2, target);
      wait_ge(fp + 3, target);
    }
    __syncthreads();
    const int bb = blockIdx.x;
    const float* hf = &g_hbuf[(kS - 1) % 3][bb * kH];
#pragma unroll
    for (int j = 0; j < 8; ++j) {
      const int oo = wid * 8 + j;
      float p = 0.f;
#pragma unroll
      for (int m = 0; m < 8; ++m) {
        p += __ldcg(&hf[lane + 32 * m]) * ow[oo * kH + lane + 32 * m];
      }
#pragma unroll
      for (int off = 16; off; off >>= 1) p += __shfl_xor_sync(0xffffffffu, p, off);
      if (lane == 0) out[bb * kO + oo] = p + ob[oo];
    }
  }
}

extern "C" void kernel_launch(void* const* d_in, const int* in_sizes, int n_in,
                              void* d_out, int out_size) {
  (void)in_sizes; (void)n_in; (void)out_size;
  stpn_kernel<<<NCTA, NTHR>>>(
      (const float*)d_in[0],
      (const float*)d_in[1],
      (const float*)d_in[2],
      (const float*)d_in[3],
      (const float*)d_in[4],
      (const float*)d_in[5],
      (const float*)d_in[6],
      (float*)d_out);
}

// round 8
// speedup vs baseline: 1.7480x; 1.7480x over previous
#include <cuda_runtime.h>

// Persistent STPN with GROUP-LOCAL sync: 16 independent groups x 8 CTAs,
// each group owns 2 batches. CTA rank c holds h-rows [32c,32c+32) x 2 batches
// as u = w + f in registers. Warp = (2 rows, 2 batches): weights shared
// across batches, ti shared across rows. Sync = 8-flag acquire poll (R4's
// proven lockstep mechanics, scope shrunk 128 -> 8 CTAs; groups independent).

#define NCTA 128
#define NTHR 512
#define GSZ 8

namespace {
constexpr int kB = 32;
constexpr int kS = 64;
constexpr int kI = 256;
constexpr int kH = 256;
constexpr int kO = 128;
constexpr int kF = 512;
constexpr int kRows = 32;   // h-rows per CTA
}

typedef unsigned long long u64;

__device__ unsigned g_flags[NCTA];      // monotonic steps completed per CTA
__device__ float g_hbuf[3][kB * kH];    // triple-buffered hidden state

__device__ __forceinline__ unsigned ld_acq(const unsigned* p) {
  unsigned v;
  asm volatile("ld.acquire.gpu.u32 %0, [%1];" : "=r"(v) : "l"(p) : "memory");
  return v;
}
__device__ __forceinline__ void st_rel(unsigned* p, unsigned v) {
  asm volatile("st.release.gpu.u32 [%0], %1;" :: "l"(p), "r"(v) : "memory");
}
__device__ __forceinline__ u64 fma2(u64 a, u64 b, u64 c) {
  u64 d; asm("fma.rn.f32x2 %0, %1, %2, %3;" : "=l"(d) : "l"(a), "l"(b), "l"(c));
  return d;
}
__device__ __forceinline__ u64 mul2(u64 a, u64 b) {
  u64 d; asm("mul.rn.f32x2 %0, %1, %2;" : "=l"(d) : "l"(a), "l"(b));
  return d;
}
__device__ __forceinline__ u64 pack2(float lo, float hi) {
  u64 d; asm("mov.b64 %0, {%1, %2};" : "=l"(d) : "f"(lo), "f"(hi));
  return d;
}
__device__ __forceinline__ float2 unpack2(u64 v) {
  float2 r; asm("mov.b64 {%0, %1}, %2;" : "=f"(r.x), "=f"(r.y) : "l"(v));
  return r;
}
__device__ __forceinline__ float tanh_fast(float z) {
  float e = __expf(2.0f * z);
  return 1.0f - __fdividef(2.0f, e + 1.0f);
}

extern __shared__ float smem_dyn[];  // sw[32*512] | sl[32*512] | sg[32*512]

__global__ void __launch_bounds__(NTHR, 1) stpn_kernel(
    const float* __restrict__ x,
    const float* __restrict__ W,
    const float* __restrict__ Lm,
    const float* __restrict__ Gm,
    const float* __restrict__ bias,
    const float* __restrict__ ow,
    const float* __restrict__ ob,
    float* __restrict__ out)
{
  float* sw = smem_dyn;
  float* sl = sw + kRows * kF;
  float* sg = sl + kRows * kF;
  __shared__ unsigned s_base;

  const int tid  = threadIdx.x;
  const int lane = tid & 31;
  const int wid  = tid >> 5;          // 0..15
  const int gid  = blockIdx.x >> 3;   // group 0..15
  const int rank = blockIdx.x & 7;    // 0..7 within group
  const int b0   = gid * 2;           // this group's two batches
  const int grow0 = rank * kRows;     // this CTA's first global h-row
  const int lr0  = 2 * wid;           // this warp's first local row
  const int row0 = grow0 + lr0;       // global rows row0, row0+1

  // stage this CTA's 32 weight rows (same rows serve both batches)
  for (int i = tid; i < kRows * kF; i += NTHR) {
    const int r = i >> 9, c = i & 511;
    sw[i] = W[(grow0 + r) * kF + c];
    sl[i] = Lm[(grow0 + r) * kF + c];
    sg[i] = Gm[(grow0 + r) * kF + c];
  }
  if (tid == 0) s_base = __ldcg(&g_flags[blockIdx.x]);
  const float bias0 = bias[row0];
  const float bias1 = bias[row0 + 1];
  __syncthreads();
  const unsigned base = s_base;

  const u64* swp0 = (const u64*)(sw + lr0 * kF);        // 256 u64 per row
  const u64* swp1 = (const u64*)(sw + (lr0 + 1) * kF);
  const u64* slp0 = (const u64*)(sl + lr0 * kF);
  const u64* slp1 = (const u64*)(sl + (lr0 + 1) * kF);
  const u64* sgp0 = (const u64*)(sg + lr0 * kF);
  const u64* sgp1 = (const u64*)(sg + (lr0 + 1) * kF);

  // state u = w + f: uu[row r][batch b][q]; q=2k+j covers u64 idx 64k+2*lane+j
  u64 uu[2][2][8];
#pragma unroll
  for (int q = 0; q < 8; ++q) {
    const int p = 64 * (q >> 1) + 2 * lane + (q & 1);
    const u64 w0 = swp0[p], w1 = swp1[p];
    uu[0][0][q] = w0; uu[0][1][q] = w0;
    uu[1][0][q] = w1; uu[1][1][q] = w1;
  }

  // initial inv-norms (per row; batch-independent at t=0)
  float iv[2][2];
#pragma unroll
  for (int r = 0; r < 2; ++r) {
    u64 sp = mul2(uu[r][0][0], uu[r][0][0]);
#pragma unroll
    for (int q = 1; q < 8; ++q) sp = fma2(uu[r][0][q], uu[r][0][q], sp);
    float2 a = unpack2(sp);
    float s = a.x + a.y;
#pragma unroll
    for (int off = 16; off; off >>= 1) s += __shfl_xor_sync(0xffffffffu, s, off);
    const float v = rsqrtf(s);
    iv[r][0] = v; iv[r][1] = v;
  }

  float hn[2][2] = {{0.f, 0.f}, {0.f, 0.f}};
  int wb = 0, rb = 2;

  for (int t = 0; t < kS; ++t) {
    // ---- group-local wait: 8 flags (tids 0..7), then CTA barrier ----
    if (t > 0) {
      if (tid < GSZ) {
        const unsigned tg = base + (unsigned)t;
        const unsigned* fp = &g_flags[gid * GSZ + tid];
        while ((int)(ld_acq(fp) - tg) < 0) { }
      }
      __syncthreads();
    }

    // ---- pre[r][b] = ti[b] . u[r][b] ----
    u64 acc00, acc01, acc10, acc11;
    {
      const u64* xpa = (const u64*)(x + ((size_t)b0 * kS + t) * kI);
      const u64* xpb = (const u64*)(x + ((size_t)(b0 + 1) * kS + t) * kI);
      const u64* hpa = (const u64*)(&g_hbuf[rb][b0 * kH]);
      const u64* hpb = (const u64*)(&g_hbuf[rb][(b0 + 1) * kH]);
      u64 ta0 = xpa[2 * lane],      ta1 = xpa[2 * lane + 1];
      u64 ta2 = xpa[64 + 2 * lane], ta3 = xpa[64 + 2 * lane + 1];
      u64 tb0 = xpb[2 * lane],      tb1 = xpb[2 * lane + 1];
      u64 tb2 = xpb[64 + 2 * lane], tb3 = xpb[64 + 2 * lane + 1];
      u64 ha0 = 0, ha1 = 0, ha2 = 0, ha3 = 0;
      u64 hb0 = 0, hb1 = 0, hb2 = 0, hb3 = 0;
      if (t > 0) {
        ha0 = __ldcg(hpa + 2 * lane);      ha1 = __ldcg(hpa + 2 * lane + 1);
        ha2 = __ldcg(hpa + 64 + 2 * lane); ha3 = __ldcg(hpa + 64 + 2 * lane + 1);
        hb0 = __ldcg(hpb + 2 * lane);      hb1 = __ldcg(hpb + 2 * lane + 1);
        hb2 = __ldcg(hpb + 64 + 2 * lane); hb3 = __ldcg(hpb + 64 + 2 * lane + 1);
      }
      acc00 = mul2(ta0, uu[0][0][0]);  acc10 = mul2(ta0, uu[1][0][0]);
      acc01 = mul2(tb0, uu[0][1][0]);  acc11 = mul2(tb0, uu[1][1][0]);
      acc00 = fma2(ta1, uu[0][0][1], acc00);  acc10 = fma2(ta1, uu[1][0][1], acc10);
      acc01 = fma2(tb1, uu[0][1][1], acc01);  acc11 = fma2(tb1, uu[1][1][1], acc11);
      acc00 = fma2(ta2, uu[0][0][2], acc00);  acc10 = fma2(ta2, uu[1][0][2], acc10);
      acc01 = fma2(tb2, uu[0][1][2], acc01);  acc11 = fma2(tb2, uu[1][1][2], acc11);
      acc00 = fma2(ta3, uu[0][0][3], acc00);  acc10 = fma2(ta3, uu[1][0][3], acc10);
      acc01 = fma2(tb3, uu[0][1][3], acc01);  acc11 = fma2(tb3, uu[1][1][3], acc11);
      acc00 = fma2(ha0, uu[0][0][4], acc00);  acc10 = fma2(ha0, uu[1][0][4], acc10);
      acc01 = fma2(hb0, uu[0][1][4], acc01);  acc11 = fma2(hb0, uu[1][1][4], acc11);
      acc00 = fma2(ha1, uu[0][0][5], acc00);  acc10 = fma2(ha1, uu[1][0][5], acc10);
      acc01 = fma2(hb1, uu[0][1][5], acc01);  acc11 = fma2(hb1, uu[1][1][5], acc11);
      acc00 = fma2(ha2, uu[0][0][6], acc00);  acc10 = fma2(ha2, uu[1][0][6], acc10);
      acc01 = fma2(hb2, uu[0][1][6], acc01);  acc11 = fma2(hb2, uu[1][1][6], acc11);
      acc00 = fma2(ha3, uu[0][0][7], acc00);  acc10 = fma2(ha3, uu[1][0][7], acc10);
      acc01 = fma2(hb3, uu[0][1][7], acc01);  acc11 = fma2(hb3, uu[1][1][7], acc11);
    }
    float2 a00 = unpack2(acc00), a01 = unpack2(acc01);
    float2 a10 = unpack2(acc10), a11 = unpack2(acc11);
    float p00 = a00.x + a00.y, p01 = a01.x + a01.y;
    float p10 = a10.x + a10.y, p11 = a11.x + a11.y;
#pragma unroll
    for (int off = 16; off; off >>= 1) {
      p00 += __shfl_xor_sync(0xffffffffu, p00, off);
      p01 += __shfl_xor_sync(0xffffffffu, p01, off);
      p10 += __shfl_xor_sync(0xffffffffu, p10, off);
      p11 += __shfl_xor_sync(0xffffffffu, p11, off);
    }
    hn[0][0] = tanh_fast(fmaf(p00, iv[0][0], bias0));
    hn[0][1] = tanh_fast(fmaf(p01, iv[0][1], bias0));
    hn[1][0] = tanh_fast(fmaf(p10, iv[1][0], bias1));
    hn[1][1] = tanh_fast(fmaf(p11, iv[1][1], bias1));

    // ---- publish h (rows row0, row0+1 adjacent -> one u64 per batch) ----
    if (lane == 0) {
      __stcg((u64*)&g_hbuf[wb][b0 * kH + row0],       pack2(hn[0][0], hn[1][0]));
      __stcg((u64*)&g_hbuf[wb][(b0 + 1) * kH + row0], pack2(hn[0][1], hn[1][1]));
    }
    __syncthreads();
    if (tid == 0) st_rel(&g_flags[blockIdx.x], base + (unsigned)(t + 1));

    // ---- shadow: u' = w + (lam*iv)*(u-w) + (gam*hn)*ti ; accumulate sq ----
    {
      const u64 n1 = pack2(-1.0f, -1.0f);
      u64 ivp[2][2], ghp[2][2], sq[2][2];
#pragma unroll
      for (int r = 0; r < 2; ++r)
#pragma unroll
        for (int b = 0; b < 2; ++b) {
          ivp[r][b] = pack2(iv[r][b], iv[r][b]);
          ghp[r][b] = pack2(hn[r][b], hn[r][b]);
          sq[r][b]  = 0;
        }
#pragma unroll
      for (int k = 0; k < 4; ++k) {
        const int p = 64 * k + 2 * lane;
        const u64 w00 = swp0[p], w01 = swp0[p + 1];
        const u64 w10 = swp1[p], w11 = swp1[p + 1];
        const u64 l00 = slp0[p], l01 = slp0[p + 1];
        const u64 l10 = slp1[p], l11 = slp1[p + 1];
        const u64 g00 = sgp0[p], g01 = sgp0[p + 1];
        const u64 g10 = sgp1[p], g11 = sgp1[p + 1];
#pragma unroll
        for (int b = 0; b < 2; ++b) {
          u64 ti0, ti1;
          if (k < 2) {
            const u64* xp = (const u64*)(x + ((size_t)(b0 + b) * kS + t) * kI);
            ti0 = xp[64 * k + 2 * lane];
            ti1 = xp[64 * k + 2 * lane + 1];
          } else if (t > 0) {
            const u64* hp = (const u64*)(&g_hbuf[rb][(b0 + b) * kH]);
            ti0 = __ldcg(hp + 64 * (k - 2) + 2 * lane);
            ti1 = __ldcg(hp + 64 * (k - 2) + 2 * lane + 1);
          } else {
            ti0 = 0; ti1 = 0;
          }
#pragma unroll
          for (int r = 0; r < 2; ++r) {
            const u64 wA = r ? w10 : w00, wB = r ? w11 : w01;
            const u64 lA = r ? l10 : l00, lB = r ? l11 : l01;
            const u64 gA = r ? g10 : g00, gB = r ? g11 : g01;
            u64& Ua = uu[r][b][2 * k];
            u64& Ub = uu[r][b][2 * k + 1];
            {
              const u64 a = mul2(lA, ivp[r][b]);
              const u64 d = fma2(n1, wA, Ua);
              const u64 e = fma2(mul2(gA, ghp[r][b]), ti0, wA);
              Ua = fma2(a, d, e);
              sq[r][b] = fma2(Ua, Ua, sq[r][b]);
            }
            {
              const u64 a = mul2(lB, ivp[r][b]);
              const u64 d = fma2(n1, wB, Ub);
              const u64 e = fma2(mul2(gB, ghp[r][b]), ti1, wB);
              Ub = fma2(a, d, e);
              sq[r][b] = fma2(Ub, Ub, sq[r][b]);
            }
          }
        }
      }
      float s00, s01, s10, s11;
      { float2 a = unpack2(sq[0][0]); s00 = a.x + a.y; }
      { float2 a = unpack2(sq[0][1]); s01 = a.x + a.y; }
      { float2 a = unpack2(sq[1][0]); s10 = a.x + a.y; }
      { float2 a = unpack2(sq[1][1]); s11 = a.x + a.y; }
#pragma unroll
      for (int off = 16; off; off >>= 1) {
        s00 += __shfl_xor_sync(0xffffffffu, s00, off);
        s01 += __shfl_xor_sync(0xffffffffu, s01, off);
        s10 += __shfl_xor_sync(0xffffffffu, s10, off);
        s11 += __shfl_xor_sync(0xffffffffu, s11, off);
      }
      iv[0][0] = rsqrtf(s00); iv[0][1] = rsqrtf(s01);
      iv[1][0] = rsqrtf(s10); iv[1][1] = rsqrtf(s11);
    }

    rb = wb;
    wb = (wb == 2) ? 0 : wb + 1;
  }

  // ---------------- epilogue ----------------
  // f_fin = u - w
  {
    const u64 n1 = pack2(-1.0f, -1.0f);
    u64* fout = (u64*)(out + kB * kO + kB * kH);
#pragma unroll
    for (int r = 0; r < 2; ++r) {
      const u64* swr = r ? swp1 : swp0;
#pragma unroll
      for (int b = 0; b < 2; ++b) {
        u64* rowp = fout + (size_t)((b0 + b) * kH + row0 + r) * (kF / 2);
#pragma unroll
        for (int q = 0; q < 8; ++q) {
          const int p = 64 * (q >> 1) + 2 * lane + (q & 1);
          rowp[p] = fma2(n1, swr[p], uu[r][b][q]);
        }
      }
    }
  }
  // h_fin
  if (lane == 0) {
    *(u64*)&out[kB * kO + b0 * kH + row0]       = pack2(hn[0][0], hn[1][0]);
    *(u64*)&out[kB * kO + (b0 + 1) * kH + row0] = pack2(hn[0][1], hn[1][1]);
  }

  // tag_space: ranks 0,1 of each group compute batch b0+rank (group-local h)
  if (rank < 2) {
    if (tid < GSZ) {
      const unsigned tg = base + (unsigned)kS;
      const unsigned* fp = &g_flags[gid * GSZ + tid];
      while ((int)(ld_acq(fp) - tg) < 0) { }
    }
    __syncthreads();
    const int bb = b0 + rank;
    const float* hf = &g_hbuf[(kS - 1) % 3][bb * kH];
#pragma unroll
    for (int j = 0; j < 8; ++j) {
      const int oo = wid * 8 + j;
      float p = 0.f;
#pragma unroll
      for (int m = 0; m < 8; ++m) {
        p += __ldcg(&hf[lane + 32 * m]) * ow[oo * kH + lane + 32 * m];
      }
#pragma unroll
      for (int off = 16; off; off >>= 1) p += __shfl_xor_sync(0xffffffffu, p, off);
      if (lane == 0) out[bb * kO + oo] = p + ob[oo];
    }
  }
}

extern "C" void kernel_launch(void* const* d_in, const int* in_sizes, int n_in,
                              void* d_out, int out_size) {
  (void)in_sizes; (void)n_in; (void)out_size;
  const int smem_bytes = 3 * kRows * kF * (int)sizeof(float);  // 196608
  cudaFuncSetAttribute(stpn_kernel,
                       cudaFuncAttributeMaxDynamicSharedMemorySize, smem_bytes);
  stpn_kernel<<<NCTA, NTHR, smem_bytes>>>(
      (const float*)d_in[0],
      (const float*)d_in[1],
      (const float*)d_in[2],
      (const float*)d_in[3],
      (const float*)d_in[4],
      (const float*)d_in[5],
      (const float*)d_in[6],
      (float*)d_out);
}